// round 1
// baseline (speedup 1.0000x reference)
#include <cuda_runtime.h>
#include <math.h>

// Problem constants
#define B_   128
#define C_   2048
#define S_   196      // H*W = 14*14
#define T_   20
#define HID_ 1024

// Scratch (device globals — no allocations allowed)
__device__ float g_vi[B_ * S_ * HID_];   // tanh(l1(vi))  ~102.8 MB
__device__ float g_u[B_ * HID_];
__device__ float g_q[B_ * HID_];
__device__ float g_u2[B_ * HID_];

// ---------------------------------------------------------------------------
// K1: u[b,h] = mean_t v_q[b,t,h]
// ---------------------------------------------------------------------------
__global__ __launch_bounds__(256) void mean_kernel(const float* __restrict__ vq,
                                                   float* __restrict__ u) {
    int idx = blockIdx.x * 256 + threadIdx.x;           // B*HID = 131072
    if (idx >= B_ * HID_) return;
    int b = idx >> 10;
    int h = idx & (HID_ - 1);
    const float* p = vq + (size_t)b * T_ * HID_ + h;
    float s = 0.f;
#pragma unroll
    for (int t = 0; t < T_; t++) s += p[(size_t)t * HID_];
    u[idx] = s * (1.0f / T_);
}

// ---------------------------------------------------------------------------
// K2: vi[m, n] = tanh( sum_c A[m,c] * l1_w[n,c] + l1_b[n] )
//     m = b*196 + s (flattened, tiles never padded: 25088 = 392*64)
//     A[m,c] = v_i[b*C*S + c*S + s]  (gathered transpose, coalesced along s)
// 64x64 tile, BK=16, 256 threads, 4x4 microtile.
// ---------------------------------------------------------------------------
__global__ __launch_bounds__(256) void gemm1_kernel(const float* __restrict__ vin,
                                                    const float* __restrict__ w,
                                                    const float* __restrict__ bias,
                                                    float* __restrict__ out) {
    __shared__ float As[16][64];   // As[c][m]
    __shared__ float Bs[16][68];   // Bs[c][n], padded to 68 (alignment + banks)

    const int m0 = blockIdx.x * 64;
    const int n0 = blockIdx.y * 64;
    const int tid = threadIdx.x;
    const int tx = tid & 15, ty = tid >> 4;

    // A-load mapping: each thread owns one row m, loads 4 c's per K-step
    const int lm = tid & 63;
    const int lcA = tid >> 6;                 // 0..3
    {
    }
    const int m = m0 + lm;
    const int b = m / S_;
    const int s = m - b * S_;
    const float* aBase = vin + (size_t)b * C_ * S_ + s;   // + c*S_

    // B-load mapping
    const int lcB = tid & 15;
    const int lnB = tid >> 4;                 // 0..15

    float acc[4][4] = {};

    for (int c0 = 0; c0 < C_; c0 += 16) {
#pragma unroll
        for (int i = 0; i < 4; i++) {
            int c = lcA + i * 4;
            As[c][lm] = aBase[(size_t)(c0 + c) * S_];
        }
#pragma unroll
        for (int i = 0; i < 4; i++) {
            int n = lnB + i * 16;
            Bs[lcB][n] = w[(size_t)(n0 + n) * C_ + c0 + lcB];
        }
        __syncthreads();
#pragma unroll
        for (int kk = 0; kk < 16; kk++) {
            float4 av = *(const float4*)&As[kk][ty * 4];
            float4 bv = *(const float4*)&Bs[kk][tx * 4];
            float a_[4] = {av.x, av.y, av.z, av.w};
            float b_[4] = {bv.x, bv.y, bv.z, bv.w};
#pragma unroll
            for (int i = 0; i < 4; i++)
#pragma unroll
                for (int j = 0; j < 4; j++) acc[i][j] += a_[i] * b_[j];
        }
        __syncthreads();
    }

    // epilogue: tanh(acc + bias) -> vi[b, s, n]
#pragma unroll
    for (int i = 0; i < 4; i++) {
        int mm = m0 + ty * 4 + i;
        int bb = mm / S_;
        int ss = mm - bb * S_;
        float* orow = out + (size_t)bb * S_ * HID_ + (size_t)ss * HID_ + n0 + tx * 4;
#pragma unroll
        for (int j = 0; j < 4; j++)
            orow[j] = tanhf(acc[i][j] + bias[n0 + tx * 4 + j]);
    }
}

// ---------------------------------------------------------------------------
// K3: q[b,k] = sum_h u[b,h] * w_u[k,h] + b_u[k]    (M=128, N=1024, K=1024)
// Same 64x64 skeleton, plain row-major A.
// ---------------------------------------------------------------------------
__global__ __launch_bounds__(256) void gemmq_kernel(const float* __restrict__ u,
                                                    const float* __restrict__ w,
                                                    const float* __restrict__ bias,
                                                    float* __restrict__ out) {
    __shared__ float As[16][64];
    __shared__ float Bs[16][68];

    const int m0 = blockIdx.x * 64;
    const int n0 = blockIdx.y * 64;
    const int tid = threadIdx.x;
    const int tx = tid & 15, ty = tid >> 4;

    const int lm = tid & 63;
    const int lcA = tid >> 6;
    const int lcB = tid & 15;
    const int lnB = tid >> 4;

    float acc[4][4] = {};

    for (int c0 = 0; c0 < HID_; c0 += 16) {
#pragma unroll
        for (int i = 0; i < 4; i++) {
            int c = lcA + i * 4;
            As[c][lm] = u[(size_t)(m0 + lm) * HID_ + c0 + c];
        }
#pragma unroll
        for (int i = 0; i < 4; i++) {
            int n = lnB + i * 16;
            Bs[lcB][n] = w[(size_t)(n0 + n) * HID_ + c0 + lcB];
        }
        __syncthreads();
#pragma unroll
        for (int kk = 0; kk < 16; kk++) {
            float4 av = *(const float4*)&As[kk][ty * 4];
            float4 bv = *(const float4*)&Bs[kk][tx * 4];
            float a_[4] = {av.x, av.y, av.z, av.w};
            float b_[4] = {bv.x, bv.y, bv.z, bv.w};
#pragma unroll
            for (int i = 0; i < 4; i++)
#pragma unroll
                for (int j = 0; j < 4; j++) acc[i][j] += a_[i] * b_[j];
        }
        __syncthreads();
    }

#pragma unroll
    for (int i = 0; i < 4; i++) {
        float* orow = out + (size_t)(m0 + ty * 4 + i) * HID_ + n0 + tx * 4;
#pragma unroll
        for (int j = 0; j < 4; j++)
            orow[j] = acc[i][j] + bias[n0 + tx * 4 + j];
    }
}

// ---------------------------------------------------------------------------
// K4: fused attention hop.
// Per CTA: (k-tile of 64 cols, one batch b).
//   t[s,k]  = sum_h vi[b,s,h] * w_vi[k,h]          (full S=196 strip)
//   e[s,k]  = exp(tanh(t + q[b,k]))                (tanh in [-1,1] -> no max pass)
//   uout[b,k] = uin[b,k] + (sum_s e*vi[b,s,k]) / (sum_s e)
// Threads: 256 = (tx:16 over N, ty:16 over M), each thread 13 rows x 4 cols.
// ---------------------------------------------------------------------------
__global__ __launch_bounds__(256) void hop_kernel(const float* __restrict__ vi,
                                                  const float* __restrict__ w,
                                                  const float* __restrict__ q,
                                                  const float* __restrict__ uin,
                                                  float* __restrict__ uout) {
    __shared__ float As[208][17];   // As[s][c], 208 rows (196 + pad), +1 col pad
    __shared__ float Bs[16][68];    // Bs[c][k]
    __shared__ float redE[16][64];
    __shared__ float redW[16][64];

    const int b = blockIdx.y;
    const int n0 = blockIdx.x * 64;
    const int tid = threadIdx.x;
    const int tx = tid & 15, ty = tid >> 4;
    const float* aB = vi + (size_t)b * S_ * HID_;

    const int lcB = tid & 15;
    const int lnB = tid >> 4;

    float acc[13][4] = {};

    for (int c0 = 0; c0 < HID_; c0 += 16) {
        // A tile: 196 x 16 (As[s][c] = vi[b, s, c0+c]) — coalesced along c
        for (int i = tid; i < S_ * 16; i += 256) {
            int s = i >> 4, c = i & 15;
            As[s][c] = aB[(size_t)s * HID_ + c0 + c];
        }
#pragma unroll
        for (int i = 0; i < 4; i++) {
            int n = lnB + i * 16;
            Bs[lcB][n] = w[(size_t)(n0 + n) * HID_ + c0 + lcB];
        }
        __syncthreads();
#pragma unroll
        for (int kk = 0; kk < 16; kk++) {
            float4 bv = *(const float4*)&Bs[kk][tx * 4];
#pragma unroll
            for (int i = 0; i < 13; i++) {
                float a = As[ty * 13 + i][kk];   // rows >=196 read pad (unused)
                acc[i][0] += a * bv.x;
                acc[i][1] += a * bv.y;
                acc[i][2] += a * bv.z;
                acc[i][3] += a * bv.w;
            }
        }
        __syncthreads();
    }

    // epilogue: exp(tanh(.+q)), two running sums per column
    float qv[4];
#pragma unroll
    for (int j = 0; j < 4; j++) qv[j] = q[(size_t)b * HID_ + n0 + tx * 4 + j];

    float E[4] = {}, W[4] = {};
#pragma unroll
    for (int i = 0; i < 13; i++) {
        int s = ty * 13 + i;
        if (s < S_) {
            float4 vv = *(const float4*)(aB + (size_t)s * HID_ + n0 + tx * 4);
            float vvv[4] = {vv.x, vv.y, vv.z, vv.w};
#pragma unroll
            for (int j = 0; j < 4; j++) {
                float e = expf(tanhf(acc[i][j] + qv[j]));
                E[j] += e;
                W[j] += e * vvv[j];
            }
        }
    }
    *(float4*)&redE[ty][tx * 4] = make_float4(E[0], E[1], E[2], E[3]);
    *(float4*)&redW[ty][tx * 4] = make_float4(W[0], W[1], W[2], W[3]);
    __syncthreads();

    if (ty == 0) {
#pragma unroll
        for (int j = 0; j < 4; j++) {
            float e = 0.f, wsum = 0.f;
#pragma unroll
            for (int t = 0; t < 16; t++) {
                e += redE[t][tx * 4 + j];
                wsum += redW[t][tx * 4 + j];
            }
            int k = n0 + tx * 4 + j;
            uout[(size_t)b * HID_ + k] = uin[(size_t)b * HID_ + k] + wsum / e;
        }
    }
}

// ---------------------------------------------------------------------------
extern "C" void kernel_launch(void* const* d_in, const int* in_sizes, int n_in,
                              void* d_out, int out_size) {
    const float* v_i  = (const float*)d_in[0];
    const float* v_q  = (const float*)d_in[1];
    const float* l1_w = (const float*)d_in[2];
    const float* l1_b = (const float*)d_in[3];
    const float* w_vi0 = (const float*)d_in[4];
    const float* w_u0  = (const float*)d_in[5];
    const float* b_u0  = (const float*)d_in[6];
    const float* w_vi1 = (const float*)d_in[7];
    const float* w_u1  = (const float*)d_in[8];
    const float* b_u1  = (const float*)d_in[9];
    float* out = (float*)d_out;

    float *vi_p, *u_p, *q_p, *u2_p;
    cudaGetSymbolAddress((void**)&vi_p, g_vi);
    cudaGetSymbolAddress((void**)&u_p, g_u);
    cudaGetSymbolAddress((void**)&q_p, g_q);
    cudaGetSymbolAddress((void**)&u2_p, g_u2);

    // u0 = mean_t(v_q)
    mean_kernel<<<(B_ * HID_ + 255) / 256, 256>>>(v_q, u_p);
    // vi = tanh(l1(v_i))
    gemm1_kernel<<<dim3(392, 16), 256>>>(v_i, l1_w, l1_b, vi_p);
    // hop 0
    gemmq_kernel<<<dim3(2, 16), 256>>>(u_p, w_u0, b_u0, q_p);
    hop_kernel<<<dim3(16, B_), 256>>>(vi_p, w_vi0, q_p, u_p, u2_p);
    // hop 1
    gemmq_kernel<<<dim3(2, 16), 256>>>(u2_p, w_u1, b_u1, q_p);
    hop_kernel<<<dim3(16, B_), 256>>>(vi_p, w_vi1, q_p, u2_p, out);
}

// round 2
// speedup vs baseline: 1.8354x; 1.8354x over previous
#include <cuda_runtime.h>
#include <math.h>
#include <stdint.h>

// Problem constants
#define B_    128
#define C_    2048
#define S_    196
#define T_    20
#define HID_  1024
#define M_TOT (B_ * S_)          // 25088 = 196 tiles of 128, no padding needed

// Scratch (device globals; no allocations allowed)
__device__ float g_vi[M_TOT * HID_];   // tanh(l1(v_i))   ~103 MB
__device__ float g_e [M_TOT * HID_];   // exp(tanh(...))  ~103 MB
__device__ float g_u [B_ * HID_];
__device__ float g_q [B_ * HID_];
__device__ float g_u2[B_ * HID_];

// ---------------------------------------------------------------------------
__device__ __forceinline__ uint32_t f2tf32(float x) {
    uint32_t r;
    asm("cvt.rna.tf32.f32 %0, %1;" : "=r"(r) : "f"(x));
    return r;
}

__device__ __forceinline__ void mma_tf32(float c[4],
                                         uint32_t a0, uint32_t a1, uint32_t a2, uint32_t a3,
                                         uint32_t b0, uint32_t b1) {
    asm volatile(
        "mma.sync.aligned.m16n8k8.row.col.f32.tf32.tf32.f32 "
        "{%0,%1,%2,%3}, {%4,%5,%6,%7}, {%8,%9}, {%0,%1,%2,%3};"
        : "+f"(c[0]), "+f"(c[1]), "+f"(c[2]), "+f"(c[3])
        : "r"(a0), "r"(a1), "r"(a2), "r"(a3), "r"(b0), "r"(b1));
}

// ---------------------------------------------------------------------------
// K1: u[b,h] = mean_t v_q[b,t,h]
// ---------------------------------------------------------------------------
__global__ __launch_bounds__(256) void mean_kernel(const float* __restrict__ vq,
                                                   float* __restrict__ u) {
    int idx = blockIdx.x * 256 + threadIdx.x;
    if (idx >= B_ * HID_) return;
    int b = idx >> 10;
    int h = idx & (HID_ - 1);
    const float* p = vq + (size_t)b * T_ * HID_ + h;
    float s = 0.f;
#pragma unroll
    for (int t = 0; t < T_; t++) s += p[(size_t)t * HID_];
    u[idx] = s * (1.0f / T_);
}

// ---------------------------------------------------------------------------
// tf32 tensor-core GEMM: out[m,n] = epi( sum_k A[m,k] * Wt[n,k] )
//   MODE 0: A gathered from v_i[b, c, s] layout;  epi = tanh(x + bias[n])
//   MODE 1: A row-major [m, K];                   epi = exp(tanh(x + q[b,n]))
// CTA tile 128x128, BK=32, 8 warps (2x4), warp tile 64x32, m16n8k8 tf32.
// Smem row stride 36 words -> bank(frag elem) = (4*row + k) % 32: conflict-free.
// ---------------------------------------------------------------------------
#define AST 36

template<int K_DIM, int MODE>
__global__ __launch_bounds__(256, 2) void mma_gemm(const float* __restrict__ A,
                                                   const float* __restrict__ Wt,
                                                   const float* __restrict__ bq,
                                                   float* __restrict__ out) {
    __shared__ uint32_t As[128 * AST];
    __shared__ uint32_t Bs[128 * AST];

    const int tid  = threadIdx.x;
    const int lane = tid & 31;
    const int warp = tid >> 5;
    const int wm   = warp >> 2;          // 0..1
    const int wn   = warp & 3;           // 0..3
    const int gid  = lane >> 2;          // 0..7
    const int tig  = lane & 3;           // 0..3

    const int n0 = blockIdx.x * 128;
    const int m0 = blockIdx.y * 128;

    // ---- A-load mapping ----
    // MODE 0: scalar, thread owns row lmA = tid&127, two k's per pass (lkA, lkA+2,..)
    const int lmA = tid & 127;
    const int lkA = tid >> 7;            // 0..1
    const float* aBase0 = nullptr;
    if (MODE == 0) {
        int m = m0 + lmA;
        int b = m / S_;
        int s = m - b * S_;
        aBase0 = A + (size_t)b * C_ * S_ + s;          // + k*S_
    }
    // MODE 1: float4 along k: kq = tid&7, mrow = tid>>3 (0..31), 4 passes
    const int lk4 = (tid & 7) * 4;
    const int lm1 = tid >> 3;            // 0..31

    // ---- B-load mapping (both modes): float4 along k ----
    const int bk4 = (tid & 7) * 4;
    const int bn  = tid >> 3;            // 0..31

    float acc[4][4][4] = {};             // [mt][nt][frag]

    for (int k0 = 0; k0 < K_DIM; k0 += 32) {
        // A tile -> As[row][k]
        if (MODE == 0) {
#pragma unroll
            for (int kk = 0; kk < 32; kk += 2) {
                float v = aBase0[(size_t)(k0 + kk + lkA) * S_];
                As[lmA * AST + kk + lkA] = f2tf32(v);
            }
        } else {
#pragma unroll
            for (int p = 0; p < 4; p++) {
                int mrow = lm1 + p * 32;
                float4 v = *(const float4*)(A + (size_t)(m0 + mrow) * K_DIM + k0 + lk4);
                uint32_t* d = &As[mrow * AST + lk4];
                d[0] = f2tf32(v.x); d[1] = f2tf32(v.y);
                d[2] = f2tf32(v.z); d[3] = f2tf32(v.w);
            }
        }
        // B tile -> Bs[n][k]
#pragma unroll
        for (int p = 0; p < 4; p++) {
            int n = bn + p * 32;
            float4 v = *(const float4*)(Wt + (size_t)(n0 + n) * K_DIM + k0 + bk4);
            uint32_t* d = &Bs[n * AST + bk4];
            d[0] = f2tf32(v.x); d[1] = f2tf32(v.y);
            d[2] = f2tf32(v.z); d[3] = f2tf32(v.w);
        }
        __syncthreads();

#pragma unroll
        for (int k8 = 0; k8 < 4; k8++) {
            const int kb = k8 * 8;
            uint32_t a[4][4], b[4][2];
#pragma unroll
            for (int mt = 0; mt < 4; mt++) {
                int row = wm * 64 + mt * 16;
                a[mt][0] = As[(row + gid)     * AST + kb + tig];
                a[mt][1] = As[(row + 8 + gid) * AST + kb + tig];
                a[mt][2] = As[(row + gid)     * AST + kb + tig + 4];
                a[mt][3] = As[(row + 8 + gid) * AST + kb + tig + 4];
            }
#pragma unroll
            for (int nt = 0; nt < 4; nt++) {
                int col = wn * 32 + nt * 8;
                b[nt][0] = Bs[(col + gid) * AST + kb + tig];
                b[nt][1] = Bs[(col + gid) * AST + kb + tig + 4];
            }
#pragma unroll
            for (int mt = 0; mt < 4; mt++)
#pragma unroll
                for (int nt = 0; nt < 4; nt++)
                    mma_tf32(acc[mt][nt], a[mt][0], a[mt][1], a[mt][2], a[mt][3],
                             b[nt][0], b[nt][1]);
        }
        __syncthreads();
    }

    // ---- epilogue ----
#pragma unroll
    for (int mt = 0; mt < 4; mt++) {
#pragma unroll
        for (int h = 0; h < 2; h++) {
            int m = m0 + wm * 64 + mt * 16 + gid + h * 8;
            float qv[8];
            if (MODE == 1) {
                int b = m / S_;
#pragma unroll
                for (int nt = 0; nt < 4; nt++) {
                    int n = n0 + wn * 32 + nt * 8 + tig * 2;
                    qv[nt * 2]     = bq[(size_t)b * HID_ + n];
                    qv[nt * 2 + 1] = bq[(size_t)b * HID_ + n + 1];
                }
            }
#pragma unroll
            for (int nt = 0; nt < 4; nt++) {
                int n = n0 + wn * 32 + nt * 8 + tig * 2;
                float x0 = acc[mt][nt][h * 2];
                float x1 = acc[mt][nt][h * 2 + 1];
                float r0, r1;
                if (MODE == 0) {
                    r0 = tanhf(x0 + bq[n]);
                    r1 = tanhf(x1 + bq[n + 1]);
                } else {
                    r0 = expf(tanhf(x0 + qv[nt * 2]));
                    r1 = expf(tanhf(x1 + qv[nt * 2 + 1]));
                }
                out[(size_t)m * HID_ + n]     = r0;
                out[(size_t)m * HID_ + n + 1] = r1;
            }
        }
    }
}

// ---------------------------------------------------------------------------
// K3: q[b,k] = sum_h u[b,h] * w_u[k,h] + b_u[k]   (tiny: 128x1024x1024)
// ---------------------------------------------------------------------------
__global__ __launch_bounds__(256) void gemmq_kernel(const float* __restrict__ u,
                                                    const float* __restrict__ w,
                                                    const float* __restrict__ bias,
                                                    float* __restrict__ out) {
    __shared__ float As[16][64];
    __shared__ float Bs[16][68];

    const int m0 = blockIdx.x * 64;
    const int n0 = blockIdx.y * 64;
    const int tid = threadIdx.x;
    const int tx = tid & 15, ty = tid >> 4;
    const int lm = tid & 63;
    const int lcA = tid >> 6;
    const int lcB = tid & 15;
    const int lnB = tid >> 4;

    float acc[4][4] = {};

    for (int c0 = 0; c0 < HID_; c0 += 16) {
#pragma unroll
        for (int i = 0; i < 4; i++) {
            int c = lcA + i * 4;
            As[c][lm] = u[(size_t)(m0 + lm) * HID_ + c0 + c];
        }
#pragma unroll
        for (int i = 0; i < 4; i++) {
            int n = lnB + i * 16;
            Bs[lcB][n] = w[(size_t)(n0 + n) * HID_ + c0 + lcB];
        }
        __syncthreads();
#pragma unroll
        for (int kk = 0; kk < 16; kk++) {
            float4 av = *(const float4*)&As[kk][ty * 4];
            float4 bv = *(const float4*)&Bs[kk][tx * 4];
            float a_[4] = {av.x, av.y, av.z, av.w};
            float b_[4] = {bv.x, bv.y, bv.z, bv.w};
#pragma unroll
            for (int i = 0; i < 4; i++)
#pragma unroll
                for (int j = 0; j < 4; j++) acc[i][j] += a_[i] * b_[j];
        }
        __syncthreads();
    }

#pragma unroll
    for (int i = 0; i < 4; i++) {
        float* orow = out + (size_t)(m0 + ty * 4 + i) * HID_ + n0 + tx * 4;
#pragma unroll
        for (int j = 0; j < 4; j++)
            orow[j] = acc[i][j] + bias[n0 + tx * 4 + j];
    }
}

// ---------------------------------------------------------------------------
// K5: per (b,n): E = sum_s e, W = sum_s e*vi; uout = uin + W/E
// ---------------------------------------------------------------------------
__global__ __launch_bounds__(256) void hop_reduce(const float* __restrict__ e,
                                                  const float* __restrict__ vi,
                                                  const float* __restrict__ uin,
                                                  float* __restrict__ uout) {
    int b = blockIdx.x;
    int n = blockIdx.y * 256 + threadIdx.x;
    const float* ep = e  + (size_t)b * S_ * HID_ + n;
    const float* vp = vi + (size_t)b * S_ * HID_ + n;
    float E = 0.f, W = 0.f;
#pragma unroll 4
    for (int s = 0; s < S_; s++) {
        float ev = ep[(size_t)s * HID_];
        float vv = vp[(size_t)s * HID_];
        E += ev;
        W += ev * vv;
    }
    size_t idx = (size_t)b * HID_ + n;
    uout[idx] = uin[idx] + W / E;
}

// ---------------------------------------------------------------------------
extern "C" void kernel_launch(void* const* d_in, const int* in_sizes, int n_in,
                              void* d_out, int out_size) {
    const float* v_i   = (const float*)d_in[0];
    const float* v_q   = (const float*)d_in[1];
    const float* l1_w  = (const float*)d_in[2];
    const float* l1_b  = (const float*)d_in[3];
    const float* w_vi0 = (const float*)d_in[4];
    const float* w_u0  = (const float*)d_in[5];
    const float* b_u0  = (const float*)d_in[6];
    const float* w_vi1 = (const float*)d_in[7];
    const float* w_u1  = (const float*)d_in[8];
    const float* b_u1  = (const float*)d_in[9];
    float* out = (float*)d_out;

    float *vi_p, *e_p, *u_p, *q_p, *u2_p;
    cudaGetSymbolAddress((void**)&vi_p, g_vi);
    cudaGetSymbolAddress((void**)&e_p,  g_e);
    cudaGetSymbolAddress((void**)&u_p,  g_u);
    cudaGetSymbolAddress((void**)&q_p,  g_q);
    cudaGetSymbolAddress((void**)&u2_p, g_u2);

    // u0 = mean_t(v_q)
    mean_kernel<<<(B_ * HID_ + 255) / 256, 256>>>(v_q, u_p);

    // vi = tanh(l1(v_i))  — tf32 tensor cores, gathered A
    mma_gemm<C_, 0><<<dim3(8, 196), 256>>>(v_i, l1_w, l1_b, vi_p);

    // hop 0
    gemmq_kernel<<<dim3(2, 16), 256>>>(u_p, w_u0, b_u0, q_p);
    mma_gemm<HID_, 1><<<dim3(8, 196), 256>>>(vi_p, w_vi0, q_p, e_p);
    hop_reduce<<<dim3(B_, 4), 256>>>(e_p, vi_p, u_p, u2_p);

    // hop 1
    gemmq_kernel<<<dim3(2, 16), 256>>>(u2_p, w_u1, b_u1, q_p);
    mma_gemm<HID_, 1><<<dim3(8, 196), 256>>>(vi_p, w_vi1, q_p, e_p);
    hop_reduce<<<dim3(B_, 4), 256>>>(e_p, vi_p, u2_p, out);
}

// round 5
// speedup vs baseline: 4.6509x; 2.5340x over previous
#include <cuda_runtime.h>
#include <math.h>
#include <stdint.h>

// Problem constants
#define B_    128
#define C_    2048
#define S_    196
#define T_    20
#define HID_  1024
#define M_TOT (B_ * S_)          // 25088 = 196 tiles of 128

// Scratch (device globals; no allocations allowed)
__device__ float g_vi[M_TOT * HID_];   // tanh(l1(v_i))
__device__ float g_e [M_TOT * HID_];   // exp(tanh(...))
__device__ float g_u [B_ * HID_];
__device__ float g_q [B_ * HID_];
__device__ float g_u2[B_ * HID_];

// ---------------------------------------------------------------------------
__device__ __forceinline__ uint32_t smem_u32(const void* p) {
    uint32_t a;
    asm("{ .reg .u64 t; cvta.to.shared.u64 t, %1; cvt.u32.u64 %0, t; }" : "=r"(a) : "l"(p));
    return a;
}
__device__ __forceinline__ float tanha(float x) {
    float y;
    asm("tanh.approx.f32 %0, %1;" : "=f"(y) : "f"(x));
    return y;
}
__device__ __forceinline__ uint32_t packbf(float lo, float hi) {
    uint32_t r;
    asm("cvt.rn.bf16x2.f32 %0, %1, %2;" : "=r"(r) : "f"(hi), "f"(lo));
    return r;
}
__device__ __forceinline__ void ldsm_x4(uint32_t r[4], uint32_t addr) {
    asm volatile("ldmatrix.sync.aligned.m8n8.x4.shared.b16 {%0,%1,%2,%3}, [%4];"
                 : "=r"(r[0]), "=r"(r[1]), "=r"(r[2]), "=r"(r[3]) : "r"(addr));
}
__device__ __forceinline__ void mma_bf16(float c[4], const uint32_t a[4],
                                         uint32_t b0, uint32_t b1) {
    asm volatile(
        "mma.sync.aligned.m16n8k16.row.col.f32.bf16.bf16.f32 "
        "{%0,%1,%2,%3}, {%4,%5,%6,%7}, {%8,%9}, {%0,%1,%2,%3};"
        : "+f"(c[0]), "+f"(c[1]), "+f"(c[2]), "+f"(c[3])
        : "r"(a[0]), "r"(a[1]), "r"(a[2]), "r"(a[3]), "r"(b0), "r"(b1));
}

// ---------------------------------------------------------------------------
// K1: u[b,h] = mean_t v_q[b,t,h]
// ---------------------------------------------------------------------------
__global__ __launch_bounds__(256) void mean_kernel(const float* __restrict__ vq,
                                                   float* __restrict__ u) {
    int idx = blockIdx.x * 256 + threadIdx.x;
    if (idx >= B_ * HID_) return;
    int b = idx >> 10;
    int h = idx & (HID_ - 1);
    const float* p = vq + (size_t)b * T_ * HID_ + h;
    float s = 0.f;
#pragma unroll
    for (int t = 0; t < T_; t++) s += p[(size_t)t * HID_];
    u[idx] = s * (1.0f / T_);
}

// ---------------------------------------------------------------------------
// bf16 tensor GEMM: out[m,n] = epi( sum_k A[m,k] * Wt[n,k] )
//   MODE 0: A gathered from v_i[b,c,s];  epi = tanh(x + bias[n])   (precise)
//   MODE 1: A row-major [m,K];           epi = exp(tanh(x + q[b,n])) (approx)
// CTA 128x128, BK=32, 8 warps (2x4), warp tile 64x32, m16n8k16 bf16,
// ldmatrix fragments, row stride 80B (conflict-free LDSM), double-buffered.
// ---------------------------------------------------------------------------
#define RSTRIDE 80            // bytes per 32-elem bf16 row (padded from 64)
#define TILEB  (128 * RSTRIDE)

template<int K_DIM, int MODE>
__global__ __launch_bounds__(256, 2) void mma_gemm(const float* __restrict__ A,
                                                   const float* __restrict__ Wt,
                                                   const float* __restrict__ bq,
                                                   float* __restrict__ out) {
    __shared__ __align__(16) char smA[2 * TILEB];
    __shared__ __align__(16) char smB[2 * TILEB];

    const int tid  = threadIdx.x;
    const int lane = tid & 31;
    const int warp = tid >> 5;
    const int wm   = warp >> 2;          // 0..1
    const int wn   = warp & 3;           // 0..3
    const int gid  = lane >> 2;          // 0..7
    const int tig  = lane & 3;           // 0..3
    const int quad = lane >> 3;          // 0..3
    const int r8   = lane & 7;           // 0..7

    const int n0 = blockIdx.x * 128;
    const int m0 = blockIdx.y * 128;

    const uint32_t sa = smem_u32(smA);
    const uint32_t sbm = smem_u32(smB);

    // ---- A-load mapping ----
    const int lmA = tid & 127;           // MODE 0: row owner
    const int lhA = tid >> 7;            // 0..1 (k-half of 32)
    const float* a0base = nullptr;
    if (MODE == 0) {
        int m = m0 + lmA;
        int b = m / S_;
        int s = m - b * S_;
        a0base = A + (size_t)b * C_ * S_ + s;          // + k*S_
    }
    const int gr  = tid >> 2;            // MODE 1 / B: row 0..63 (x2 passes)
    const int gq  = tid & 3;             // 8-elem group within 32
    const float* aRow = (MODE == 1) ? (A + (size_t)m0 * K_DIM) : nullptr;
    const float* bRow = Wt + (size_t)n0 * K_DIM;

    // prefetch registers (converted bf16x2)
    uint32_t pa[8], pb[8];

    auto fetchA = [&](int k0) {
        if (MODE == 0) {
#pragma unroll
            for (int i = 0; i < 8; i++) {
                float v0 = a0base[(size_t)(k0 + lhA * 16 + 2 * i) * S_];
                float v1 = a0base[(size_t)(k0 + lhA * 16 + 2 * i + 1) * S_];
                pa[i] = packbf(v0, v1);
            }
        } else {
#pragma unroll
            for (int p = 0; p < 2; p++) {
                int row = gr + p * 64;
                const float* g = aRow + (size_t)row * K_DIM + k0 + gq * 8;
                float4 v0 = *(const float4*)g;
                float4 v1 = *(const float4*)(g + 4);
                pa[p * 4 + 0] = packbf(v0.x, v0.y);
                pa[p * 4 + 1] = packbf(v0.z, v0.w);
                pa[p * 4 + 2] = packbf(v1.x, v1.y);
                pa[p * 4 + 3] = packbf(v1.z, v1.w);
            }
        }
    };
    auto fetchB = [&](int k0) {
#pragma unroll
        for (int p = 0; p < 2; p++) {
            int row = gr + p * 64;
            const float* g = bRow + (size_t)row * K_DIM + k0 + gq * 8;
            float4 v0 = *(const float4*)g;
            float4 v1 = *(const float4*)(g + 4);
            pb[p * 4 + 0] = packbf(v0.x, v0.y);
            pb[p * 4 + 1] = packbf(v0.z, v0.w);
            pb[p * 4 + 2] = packbf(v1.x, v1.y);
            pb[p * 4 + 3] = packbf(v1.z, v1.w);
        }
    };
    auto storeA = [&](int buf) {
        char* base = smA + buf * TILEB;
        if (MODE == 0) {
            char* d = base + lmA * RSTRIDE + lhA * 32;
            *(uint4*)d = make_uint4(pa[0], pa[1], pa[2], pa[3]);
            *(uint4*)(d + 16) = make_uint4(pa[4], pa[5], pa[6], pa[7]);
        } else {
#pragma unroll
            for (int p = 0; p < 2; p++)
                *(uint4*)(base + (gr + p * 64) * RSTRIDE + gq * 16) =
                    make_uint4(pa[p * 4], pa[p * 4 + 1], pa[p * 4 + 2], pa[p * 4 + 3]);
        }
    };
    auto storeB = [&](int buf) {
        char* base = smB + buf * TILEB;
#pragma unroll
        for (int p = 0; p < 2; p++)
            *(uint4*)(base + (gr + p * 64) * RSTRIDE + gq * 16) =
                make_uint4(pb[p * 4], pb[p * 4 + 1], pb[p * 4 + 2], pb[p * 4 + 3]);
    };

    // ldmatrix address offsets (within a buffer), excluding k-step advance
    uint32_t offA[4], offB[2];
#pragma unroll
    for (int mt = 0; mt < 4; mt++) {
        int row = wm * 64 + mt * 16 + (quad & 1) * 8 + r8;
        offA[mt] = row * RSTRIDE + (quad >> 1) * 16;
    }
#pragma unroll
    for (int p = 0; p < 2; p++) {
        int row = wn * 32 + p * 16 + (quad >> 1) * 8 + r8;
        offB[p] = row * RSTRIDE + (quad & 1) * 16;
    }

    float acc[4][4][4] = {};
    constexpr int NT = K_DIM / 32;

    fetchA(0); fetchB(0);
    storeA(0); storeB(0);
    __syncthreads();

    for (int t = 0; t < NT; t++) {
        const int j = t & 1;
        if (t + 1 < NT) { fetchA((t + 1) * 32); fetchB((t + 1) * 32); }

        const uint32_t baA = sa + j * TILEB;
        const uint32_t baB = sbm + j * TILEB;
#pragma unroll
        for (int ks = 0; ks < 2; ks++) {
            uint32_t a[4][4], b[2][4];
#pragma unroll
            for (int mt = 0; mt < 4; mt++) ldsm_x4(a[mt], baA + offA[mt] + ks * 32);
#pragma unroll
            for (int p = 0; p < 2; p++)   ldsm_x4(b[p],  baB + offB[p] + ks * 32);
#pragma unroll
            for (int mt = 0; mt < 4; mt++)
#pragma unroll
                for (int nt = 0; nt < 4; nt++)
                    mma_bf16(acc[mt][nt], a[mt],
                             b[nt >> 1][(nt & 1) * 2], b[nt >> 1][(nt & 1) * 2 + 1]);
        }

        if (t + 1 < NT) {
            storeA(j ^ 1); storeB(j ^ 1);
        }
        __syncthreads();
    }

    // ---- epilogue (acc fragment layout: m16n8 standard) ----
#pragma unroll
    for (int mt = 0; mt < 4; mt++) {
#pragma unroll
        for (int h = 0; h < 2; h++) {
            int m = m0 + wm * 64 + mt * 16 + gid + h * 8;
            const float* qrow = (MODE == 1) ? (bq + (size_t)(m / S_) * HID_) : bq;
#pragma unroll
            for (int nt = 0; nt < 4; nt++) {
                int n = n0 + wn * 32 + nt * 8 + tig * 2;
                float x0 = acc[mt][nt][h * 2]     + qrow[n];
                float x1 = acc[mt][nt][h * 2 + 1] + qrow[n + 1];
                float r0, r1;
                if (MODE == 0) { r0 = tanhf(x0); r1 = tanhf(x1); }
                else           { r0 = __expf(tanha(x0)); r1 = __expf(tanha(x1)); }
                float2 o = make_float2(r0, r1);
                *(float2*)(out + (size_t)m * HID_ + n) = o;
            }
        }
    }
}

// ---------------------------------------------------------------------------
// K3: q[b,k] = sum_h u[b,h] * w_u[k,h] + b_u[k]   (tiny: 128x1024x1024)
// ---------------------------------------------------------------------------
__global__ __launch_bounds__(256) void gemmq_kernel(const float* __restrict__ u,
                                                    const float* __restrict__ w,
                                                    const float* __restrict__ bias,
                                                    float* __restrict__ out) {
    __shared__ float As[16][64];
    __shared__ float Bs[16][68];

    const int m0 = blockIdx.x * 64;
    const int n0 = blockIdx.y * 64;
    const int tid = threadIdx.x;
    const int tx = tid & 15, ty = tid >> 4;
    const int lm = tid & 63;
    const int lcA = tid >> 6;
    const int lcB = tid & 15;
    const int lnB = tid >> 4;

    float acc[4][4] = {};

    for (int c0 = 0; c0 < HID_; c0 += 16) {
#pragma unroll
        for (int i = 0; i < 4; i++) {
            int c = lcA + i * 4;
            As[c][lm] = u[(size_t)(m0 + lm) * HID_ + c0 + c];
        }
#pragma unroll
        for (int i = 0; i < 4; i++) {
            int n = lnB + i * 16;
            Bs[lcB][n] = w[(size_t)(n0 + n) * HID_ + c0 + lcB];
        }
        __syncthreads();
#pragma unroll
        for (int kk = 0; kk < 16; kk++) {
            float4 av = *(const float4*)&As[kk][ty * 4];
            float4 bv = *(const float4*)&Bs[kk][tx * 4];
            float a_[4] = {av.x, av.y, av.z, av.w};
            float b_[4] = {bv.x, bv.y, bv.z, bv.w};
#pragma unroll
            for (int i = 0; i < 4; i++)
#pragma unroll
                for (int j = 0; j < 4; j++) acc[i][j] += a_[i] * b_[j];
        }
        __syncthreads();
    }

#pragma unroll
    for (int i = 0; i < 4; i++) {
        float* orow = out + (size_t)(m0 + ty * 4 + i) * HID_ + n0 + tx * 4;
#pragma unroll
        for (int j = 0; j < 4; j++)
            orow[j] = acc[i][j] + bias[n0 + tx * 4 + j];
    }
}

// ---------------------------------------------------------------------------
// K5: per (b,n): E = sum_s e, W = sum_s e*vi; uout = uin + W/E
// ---------------------------------------------------------------------------
__global__ __launch_bounds__(256) void hop_reduce(const float* __restrict__ e,
                                                  const float* __restrict__ vi,
                                                  const float* __restrict__ uin,
                                                  float* __restrict__ uout) {
    int b = blockIdx.x;
    int n = blockIdx.y * 256 + threadIdx.x;
    const float* ep = e  + (size_t)b * S_ * HID_ + n;
    const float* vp = vi + (size_t)b * S_ * HID_ + n;
    float E = 0.f, W = 0.f;
#pragma unroll 4
    for (int s = 0; s < S_; s++) {
        float ev = ep[(size_t)s * HID_];
        float vv = vp[(size_t)s * HID_];
        E += ev;
        W += ev * vv;
    }
    size_t idx = (size_t)b * HID_ + n;
    uout[idx] = uin[idx] + W / E;
}

// ---------------------------------------------------------------------------
extern "C" void kernel_launch(void* const* d_in, const int* in_sizes, int n_in,
                              void* d_out, int out_size) {
    const float* v_i   = (const float*)d_in[0];
    const float* v_q   = (const float*)d_in[1];
    const float* l1_w  = (const float*)d_in[2];
    const float* l1_b  = (const float*)d_in[3];
    const float* w_vi0 = (const float*)d_in[4];
    const float* w_u0  = (const float*)d_in[5];
    const float* b_u0  = (const float*)d_in[6];
    const float* w_vi1 = (const float*)d_in[7];
    const float* w_u1  = (const float*)d_in[8];
    const float* b_u1  = (const float*)d_in[9];
    float* out = (float*)d_out;

    float *vi_p, *e_p, *u_p, *q_p, *u2_p;
    cudaGetSymbolAddress((void**)&vi_p, g_vi);
    cudaGetSymbolAddress((void**)&e_p,  g_e);
    cudaGetSymbolAddress((void**)&u_p,  g_u);
    cudaGetSymbolAddress((void**)&q_p,  g_q);
    cudaGetSymbolAddress((void**)&u2_p, g_u2);

    // u0 = mean_t(v_q)
    mean_kernel<<<(B_ * HID_ + 255) / 256, 256>>>(v_q, u_p);

    // vi = tanh(l1(v_i))
    mma_gemm<C_, 0><<<dim3(8, 196), 256>>>(v_i, l1_w, l1_b, vi_p);

    // hop 0
    gemmq_kernel<<<dim3(2, 16), 256>>>(u_p, w_u0, b_u0, q_p);
    mma_gemm<HID_, 1><<<dim3(8, 196), 256>>>(vi_p, w_vi0, q_p, e_p);
    hop_reduce<<<dim3(B_, 4), 256>>>(e_p, vi_p, u_p, u2_p);

    // hop 1
    gemmq_kernel<<<dim3(2, 16), 256>>>(u2_p, w_u1, b_u1, q_p);
    mma_gemm<HID_, 1><<<dim3(8, 196), 256>>>(vi_p, w_vi1, q_p, e_p);
    hop_reduce<<<dim3(B_, 4), 256>>>(e_p, vi_p, u2_p, out);
}

// round 6
// speedup vs baseline: 5.6369x; 1.2120x over previous
#include <cuda_runtime.h>
#include <cuda_fp16.h>
#include <math.h>
#include <stdint.h>

// Problem constants
#define B_    128
#define C_    2048
#define S_    196
#define T_    20
#define HID_  1024
#define M_TOT (B_ * S_)          // 25088 = 196 tiles of 128

// Scratch (device globals; no allocations allowed)
__device__ __half g_vt [M_TOT * C_];     // transposed v_i, fp16 [m, c]
__device__ __half g_vih[M_TOT * HID_];   // vi fp16 (hop GEMM A operand)
__device__ float  g_vi [M_TOT * HID_];   // vi fp32 (reduce)
__device__ float  g_e  [M_TOT * HID_];   // exp(tanh(...))
__device__ __half g_wl1[HID_ * C_];      // fp16 weights
__device__ __half g_w0 [HID_ * HID_];
__device__ __half g_w1 [HID_ * HID_];
__device__ float  g_u  [B_ * HID_];
__device__ float  g_q  [B_ * HID_];
__device__ float  g_u2 [B_ * HID_];

// ---------------------------------------------------------------------------
__device__ __forceinline__ uint32_t smem_u32(const void* p) {
    uint32_t a;
    asm("{ .reg .u64 t; cvta.to.shared.u64 t, %1; cvt.u32.u64 %0, t; }" : "=r"(a) : "l"(p));
    return a;
}
__device__ __forceinline__ float tanha(float x) {
    float y;
    asm("tanh.approx.f32 %0, %1;" : "=f"(y) : "f"(x));
    return y;
}
__device__ __forceinline__ void cpa16(uint32_t dst, const void* src) {
    asm volatile("cp.async.cg.shared.global [%0], [%1], 16;" :: "r"(dst), "l"(src));
}
__device__ __forceinline__ void ldsm_x4(uint32_t r[4], uint32_t addr) {
    asm volatile("ldmatrix.sync.aligned.m8n8.x4.shared.b16 {%0,%1,%2,%3}, [%4];"
                 : "=r"(r[0]), "=r"(r[1]), "=r"(r[2]), "=r"(r[3]) : "r"(addr));
}
__device__ __forceinline__ void mma_f16(float c[4], const uint32_t a[4],
                                        uint32_t b0, uint32_t b1) {
    asm volatile(
        "mma.sync.aligned.m16n8k16.row.col.f32.f16.f16.f32 "
        "{%0,%1,%2,%3}, {%4,%5,%6,%7}, {%8,%9}, {%0,%1,%2,%3};"
        : "+f"(c[0]), "+f"(c[1]), "+f"(c[2]), "+f"(c[3])
        : "r"(a[0]), "r"(a[1]), "r"(a[2]), "r"(a[3]), "r"(b0), "r"(b1));
}

// ---------------------------------------------------------------------------
// K1: u[b,h] = mean_t v_q[b,t,h]
// ---------------------------------------------------------------------------
__global__ __launch_bounds__(256) void mean_kernel(const float* __restrict__ vq,
                                                   float* __restrict__ u) {
    int idx = blockIdx.x * 256 + threadIdx.x;
    if (idx >= B_ * HID_) return;
    int b = idx >> 10;
    int h = idx & (HID_ - 1);
    const float* p = vq + (size_t)b * T_ * HID_ + h;
    float s = 0.f;
#pragma unroll
    for (int t = 0; t < T_; t++) s += p[(size_t)t * HID_];
    u[idx] = s * (1.0f / T_);
}

// ---------------------------------------------------------------------------
// fp32 -> fp16 convert (vectorized, n % 4 == 0)
// ---------------------------------------------------------------------------
__global__ __launch_bounds__(256) void cvt_kernel(const float* __restrict__ in,
                                                  __half* __restrict__ out, int n4) {
    int i = blockIdx.x * 256 + threadIdx.x;
    if (i >= n4) return;
    float4 v = *(const float4*)(in + (size_t)i * 4);
    __half2* o = (__half2*)(out + (size_t)i * 4);
    o[0] = __floats2half2_rn(v.x, v.y);
    o[1] = __floats2half2_rn(v.z, v.w);
}

// ---------------------------------------------------------------------------
// transpose v_i [b, c, s] fp32 -> vt [b*S + s, c] fp16
// ---------------------------------------------------------------------------
__global__ __launch_bounds__(256) void transpose_kernel(const float* __restrict__ vin,
                                                        __half* __restrict__ vt) {
    __shared__ float tile[32][33];
    const int c0 = blockIdx.x * 32;
    const int s0 = blockIdx.y * 32;
    const int b  = blockIdx.z;
    const int tx = threadIdx.x, ty = threadIdx.y;   // (32, 8)

#pragma unroll
    for (int i = 0; i < 4; i++) {
        int c = c0 + ty + i * 8;
        int s = s0 + tx;
        if (s < S_) tile[ty + i * 8][tx] = vin[((size_t)b * C_ + c) * S_ + s];
    }
    __syncthreads();
#pragma unroll
    for (int i = 0; i < 4; i++) {
        int s = s0 + ty + i * 8;
        int c = c0 + tx;
        if (s < S_)
            vt[((size_t)(b * S_ + s)) * C_ + c] = __float2half(tile[tx][ty + i * 8]);
    }
}

// ---------------------------------------------------------------------------
// fp16 tensor GEMM: y[m,n] = epi( sum_k A[m,k] * Wt[n,k] )
//   A fp16 [M, K] row-major, Wt fp16 [N, K] row-major. CTA 128x128, BK=32.
//   8 warps (2x4), warp tile 64x32, m16n8k16 f16, cp.async tile loads,
//   ldmatrix fragments, row stride 80B (conflict-free), double-buffered.
//   MODE 0: epi = tanh(x + bias[n]) -> out32 AND out16
//   MODE 1: epi = exp(tanh(x + q[b,n])) -> out32
// ---------------------------------------------------------------------------
#define RSTRIDE 80
#define TILEB  (128 * RSTRIDE)

template<int K_DIM, int MODE>
__global__ __launch_bounds__(256, 2) void mma_gemm(const __half* __restrict__ A,
                                                   const __half* __restrict__ Wt,
                                                   const float* __restrict__ bq,
                                                   float* __restrict__ out32,
                                                   __half* __restrict__ out16) {
    __shared__ __align__(16) char smA[2 * TILEB];
    __shared__ __align__(16) char smB[2 * TILEB];

    const int tid  = threadIdx.x;
    const int lane = tid & 31;
    const int warp = tid >> 5;
    const int wm   = warp >> 2;          // 0..1
    const int wn   = warp & 3;           // 0..3
    const int gid  = lane >> 2;          // 0..7
    const int tig  = lane & 3;           // 0..3
    const int quad = lane >> 3;          // 0..3
    const int r8   = lane & 7;           // 0..7

    const int n0 = blockIdx.x * 128;
    const int m0 = blockIdx.y * 128;

    const uint32_t sa  = smem_u32(smA);
    const uint32_t sbm = smem_u32(smB);

    // cp.async mapping: thread covers (row = tid>>2 + p*64, unit = tid&3)
    const int crow = tid >> 2;
    const int cu   = tid & 3;
    const __half* aBase = A  + (size_t)(m0 + crow) * K_DIM + cu * 8;
    const __half* bBase = Wt + (size_t)(n0 + crow) * K_DIM + cu * 8;
    const uint32_t dA = sa  + crow * RSTRIDE + cu * 16;
    const uint32_t dB = sbm + crow * RSTRIDE + cu * 16;

    auto tileLoad = [&](int k0, int buf) {
#pragma unroll
        for (int p = 0; p < 2; p++) {
            cpa16(dA + buf * TILEB + p * 64 * RSTRIDE,
                  aBase + (size_t)p * 64 * K_DIM + k0);
            cpa16(dB + buf * TILEB + p * 64 * RSTRIDE,
                  bBase + (size_t)p * 64 * K_DIM + k0);
        }
        asm volatile("cp.async.commit_group;");
    };

    // ldmatrix address offsets within a buffer
    uint32_t offA[4], offB[2];
#pragma unroll
    for (int mt = 0; mt < 4; mt++) {
        int row = wm * 64 + mt * 16 + (quad & 1) * 8 + r8;
        offA[mt] = row * RSTRIDE + (quad >> 1) * 16;
    }
#pragma unroll
    for (int p = 0; p < 2; p++) {
        int row = wn * 32 + p * 16 + (quad >> 1) * 8 + r8;
        offB[p] = row * RSTRIDE + (quad & 1) * 16;
    }

    float acc[4][4][4] = {};
    constexpr int NT = K_DIM / 32;

    tileLoad(0, 0);
    asm volatile("cp.async.wait_group 0;");
    __syncthreads();

    for (int t = 0; t < NT; t++) {
        const int j = t & 1;
        if (t + 1 < NT) tileLoad((t + 1) * 32, j ^ 1);

        const uint32_t baA = sa + j * TILEB;
        const uint32_t baB = sbm + j * TILEB;
#pragma unroll
        for (int ks = 0; ks < 2; ks++) {
            uint32_t a[4][4], b[2][4];
#pragma unroll
            for (int mt = 0; mt < 4; mt++) ldsm_x4(a[mt], baA + offA[mt] + ks * 32);
#pragma unroll
            for (int p = 0; p < 2; p++)   ldsm_x4(b[p],  baB + offB[p] + ks * 32);
#pragma unroll
            for (int mt = 0; mt < 4; mt++)
#pragma unroll
                for (int nt = 0; nt < 4; nt++)
                    mma_f16(acc[mt][nt], a[mt],
                            b[nt >> 1][(nt & 1) * 2], b[nt >> 1][(nt & 1) * 2 + 1]);
        }

        if (t + 1 < NT) {
            asm volatile("cp.async.wait_group 0;");
        }
        __syncthreads();
    }

    // ---- epilogue ----
#pragma unroll
    for (int mt = 0; mt < 4; mt++) {
#pragma unroll
        for (int h = 0; h < 2; h++) {
            int m = m0 + wm * 64 + mt * 16 + gid + h * 8;
            const float* qrow = (MODE == 1) ? (bq + (size_t)(m / S_) * HID_) : bq;
#pragma unroll
            for (int nt = 0; nt < 4; nt++) {
                int n = n0 + wn * 32 + nt * 8 + tig * 2;
                float x0 = acc[mt][nt][h * 2]     + qrow[n];
                float x1 = acc[mt][nt][h * 2 + 1] + qrow[n + 1];
                float r0, r1;
                if (MODE == 0) { r0 = tanha(x0); r1 = tanha(x1); }
                else           { r0 = __expf(tanha(x0)); r1 = __expf(tanha(x1)); }
                *(float2*)(out32 + (size_t)m * HID_ + n) = make_float2(r0, r1);
                if (MODE == 0)
                    *(__half2*)(out16 + (size_t)m * HID_ + n) = __floats2half2_rn(r0, r1);
            }
        }
    }
}

// ---------------------------------------------------------------------------
// K3: q[b,k] = sum_h u[b,h] * w_u[k,h] + b_u[k]   (tiny: 128x1024x1024, fp32)
// ---------------------------------------------------------------------------
__global__ __launch_bounds__(256) void gemmq_kernel(const float* __restrict__ u,
                                                    const float* __restrict__ w,
                                                    const float* __restrict__ bias,
                                                    float* __restrict__ out) {
    __shared__ float As[16][64];
    __shared__ float Bs[16][68];

    const int m0 = blockIdx.x * 64;
    const int n0 = blockIdx.y * 64;
    const int tid = threadIdx.x;
    const int tx = tid & 15, ty = tid >> 4;
    const int lm = tid & 63;
    const int lcA = tid >> 6;
    const int lcB = tid & 15;
    const int lnB = tid >> 4;

    float acc[4][4] = {};

    for (int c0 = 0; c0 < HID_; c0 += 16) {
#pragma unroll
        for (int i = 0; i < 4; i++) {
            int c = lcA + i * 4;
            As[c][lm] = u[(size_t)(m0 + lm) * HID_ + c0 + c];
        }
#pragma unroll
        for (int i = 0; i < 4; i++) {
            int n = lnB + i * 16;
            Bs[lcB][n] = w[(size_t)(n0 + n) * HID_ + c0 + lcB];
        }
        __syncthreads();
#pragma unroll
        for (int kk = 0; kk < 16; kk++) {
            float4 av = *(const float4*)&As[kk][ty * 4];
            float4 bv = *(const float4*)&Bs[kk][tx * 4];
            float a_[4] = {av.x, av.y, av.z, av.w};
            float b_[4] = {bv.x, bv.y, bv.z, bv.w};
#pragma unroll
            for (int i = 0; i < 4; i++)
#pragma unroll
                for (int j = 0; j < 4; j++) acc[i][j] += a_[i] * b_[j];
        }
        __syncthreads();
    }

#pragma unroll
    for (int i = 0; i < 4; i++) {
        float* orow = out + (size_t)(m0 + ty * 4 + i) * HID_ + n0 + tx * 4;
#pragma unroll
        for (int j = 0; j < 4; j++)
            orow[j] = acc[i][j] + bias[n0 + tx * 4 + j];
    }
}

// ---------------------------------------------------------------------------
// K5: per (b,n): E = sum_s e, W = sum_s e*vi; uout = uin + W/E
// ---------------------------------------------------------------------------
__global__ __launch_bounds__(256) void hop_reduce(const float* __restrict__ e,
                                                  const float* __restrict__ vi,
                                                  const float* __restrict__ uin,
                                                  float* __restrict__ uout) {
    int b = blockIdx.x;
    int n = blockIdx.y * 256 + threadIdx.x;
    const float* ep = e  + (size_t)b * S_ * HID_ + n;
    const float* vp = vi + (size_t)b * S_ * HID_ + n;
    float E = 0.f, W = 0.f;
#pragma unroll 4
    for (int s = 0; s < S_; s++) {
        float ev = ep[(size_t)s * HID_];
        float vv = vp[(size_t)s * HID_];
        E += ev;
        W += ev * vv;
    }
    size_t idx = (size_t)b * HID_ + n;
    uout[idx] = uin[idx] + W / E;
}

// ---------------------------------------------------------------------------
extern "C" void kernel_launch(void* const* d_in, const int* in_sizes, int n_in,
                              void* d_out, int out_size) {
    const float* v_i   = (const float*)d_in[0];
    const float* v_q   = (const float*)d_in[1];
    const float* l1_w  = (const float*)d_in[2];
    const float* l1_b  = (const float*)d_in[3];
    const float* w_vi0 = (const float*)d_in[4];
    const float* w_u0  = (const float*)d_in[5];
    const float* b_u0  = (const float*)d_in[6];
    const float* w_vi1 = (const float*)d_in[7];
    const float* w_u1  = (const float*)d_in[8];
    const float* b_u1  = (const float*)d_in[9];
    float* out = (float*)d_out;

    __half *vt_p, *vih_p, *wl1_p, *w0_p, *w1_p;
    float *vi_p, *e_p, *u_p, *q_p, *u2_p;
    cudaGetSymbolAddress((void**)&vt_p,  g_vt);
    cudaGetSymbolAddress((void**)&vih_p, g_vih);
    cudaGetSymbolAddress((void**)&wl1_p, g_wl1);
    cudaGetSymbolAddress((void**)&w0_p,  g_w0);
    cudaGetSymbolAddress((void**)&w1_p,  g_w1);
    cudaGetSymbolAddress((void**)&vi_p,  g_vi);
    cudaGetSymbolAddress((void**)&e_p,   g_e);
    cudaGetSymbolAddress((void**)&u_p,   g_u);
    cudaGetSymbolAddress((void**)&q_p,   g_q);
    cudaGetSymbolAddress((void**)&u2_p,  g_u2);

    // prologue: mean, weight converts, v_i transpose
    mean_kernel<<<(B_ * HID_ + 255) / 256, 256>>>(v_q, u_p);
    cvt_kernel<<<(HID_ * C_ / 4 + 255) / 256, 256>>>(l1_w, wl1_p, HID_ * C_ / 4);
    cvt_kernel<<<(HID_ * HID_ / 4 + 255) / 256, 256>>>(w_vi0, w0_p, HID_ * HID_ / 4);
    cvt_kernel<<<(HID_ * HID_ / 4 + 255) / 256, 256>>>(w_vi1, w1_p, HID_ * HID_ / 4);
    transpose_kernel<<<dim3(C_ / 32, 7, B_), dim3(32, 8)>>>(v_i, vt_p);

    // vi = tanh(l1(v_i))
    mma_gemm<C_, 0><<<dim3(8, 196), 256>>>(vt_p, wl1_p, l1_b, vi_p, vih_p);

    // hop 0
    gemmq_kernel<<<dim3(2, 16), 256>>>(u_p, w_u0, b_u0, q_p);
    mma_gemm<HID_, 1><<<dim3(8, 196), 256>>>(vih_p, w0_p, q_p, e_p, nullptr);
    hop_reduce<<<dim3(B_, 4), 256>>>(e_p, vi_p, u_p, u2_p);

    // hop 1
    gemmq_kernel<<<dim3(2, 16), 256>>>(u2_p, w_u1, b_u1, q_p);
    mma_gemm<HID_, 1><<<dim3(8, 196), 256>>>(vih_p, w1_p, q_p, e_p, nullptr);
    hop_reduce<<<dim3(B_, 4), 256>>>(e_p, vi_p, u2_p, out);
}